// round 17
// baseline (speedup 1.0000x reference)
#include <cuda_runtime.h>
#include <math.h>

#define NN 256
#define NM 240
#define NB 240
#define NT 512
#define ITERS 30
#define PER_LAUNCH (2 * NB)

typedef unsigned long long u64;
union F2 { u64 u; float2 f; };
#define ONES2 0x3f8000003f800000ULL

// ---------------- device scratch ----------------
__device__ float4   g_At4[60 * NM];    // [kb*240+j] = A[j][16+4kb..16+4kb+3]
__device__ float4   g_Ab4[60 * NM];    // [jb*240+k] = A[4jb+r][16+k]
__device__ float    g_S2buf[4][256];   // 4-slot tau-grad accumulators
__device__ float    g_Lbuf[4];         // 4-slot loss accumulators
__device__ float    g_Lp[256];         // epilogue per-block loss partials
__device__ unsigned g_gc[4];           // per-slot head-arrival counters
__device__ unsigned g_barcnt;

// ---------------- helpers ----------------
static __device__ __forceinline__ unsigned ld_acq(const unsigned* p) {
    unsigned v; asm volatile("ld.acquire.gpu.global.u32 %0,[%1];" : "=r"(v) : "l"(p)); return v;
}
static __device__ __forceinline__ float ldcg(const float* p) {
    float v; asm volatile("ld.global.cg.f32 %0,[%1];" : "=f"(v) : "l"(p)); return v;
}
static __device__ __forceinline__ float4 ldcg4(const float4* p) {
    float4 v;
    asm volatile("ld.global.cg.v4.f32 {%0,%1,%2,%3},[%4];"
                 : "=f"(v.x), "=f"(v.y), "=f"(v.z), "=f"(v.w) : "l"(p));
    return v;
}
static __device__ __forceinline__ void redadd(float* p, float v) {
    asm volatile("red.global.add.f32 [%0],%1;" :: "l"(p), "f"(v) : "memory");
}
static __device__ __forceinline__ float rcpa(float x) {
    float r; asm("rcp.approx.f32 %0,%1;" : "=f"(r) : "f"(x)); return r;
}
static __device__ __forceinline__ u64 fma2_(u64 a, u64 b, u64 c) {
    u64 d; asm("fma.rn.f32x2 %0,%1,%2,%3;" : "=l"(d) : "l"(a), "l"(b), "l"(c)); return d;
}
static __device__ __forceinline__ u64 mul2_(u64 a, u64 b) {
    u64 d; asm("mul.rn.f32x2 %0,%1,%2;" : "=l"(d) : "l"(a), "l"(b)); return d;
}
static __device__ __forceinline__ float sigm(float x) { return 1.0f / (1.0f + __expf(-x)); }

#define WRED(val, dst) do { float _v = (val);                             \
    _v += __shfl_down_sync(0xffffffffu, _v, 16);                          \
    _v += __shfl_down_sync(0xffffffffu, _v, 8);                           \
    _v += __shfl_down_sync(0xffffffffu, _v, 4);                           \
    _v += __shfl_down_sync(0xffffffffu, _v, 2);                           \
    _v += __shfl_down_sync(0xffffffffu, _v, 1);                           \
    if ((tx & 31) == 0) (dst)[tx >> 5] = _v; } while (0)

static __device__ __forceinline__ float sum8(const float* w, int g) {
    float s = 0.f;
    #pragma unroll
    for (int i = 0; i < 8; ++i) s += w[g * 8 + i];
    return s;
}

#define GRIDBAR() do { __syncthreads();                                   \
    if (tx == 0) { __threadfence(); atomicAdd(&g_barcnt, 1u);             \
        while (ld_acq(&g_barcnt) < bartgt) __nanosleep(32); }             \
    bartgt += NB; __syncthreads(); } while (0)

#define QUADACC(t01u, t23u, n01u, n23u, acc, bad) do {                    \
    F2 _t0; _t0.u = (t01u); F2 _t1; _t1.u = (t23u);                       \
    F2 _n0; _n0.u = (n01u); F2 _n1; _n1.u = (n23u);                       \
    float _P01 = _t0.f.x * _t0.f.y;                                       \
    float _P23 = _t1.f.x * _t1.f.y;                                       \
    float _T = _P01 * _P23;                                               \
    float _r = rcpa(_T);                                                  \
    float _m1 = fmaf(_n0.f.y, _t0.f.x, _n0.f.x * _t0.f.y);                \
    float _m3 = fmaf(_n1.f.y, _t1.f.x, _n1.f.x * _t1.f.y);                \
    float _s = fmaf(_m3, _P01, _m1 * _P23);                               \
    bool _ok = (_T != 0.f);                                               \
    acc += _ok ? _s * _r : 0.f;                                           \
    bad |= !_ok; } while (0)

// ---------------- persistent kernel: 240 blocks x 512 thr, 1 row/block ----
__global__ void __launch_bounds__(NT, 2) gflow(
    const float* __restrict__ A, const float* __restrict__ Gl0,
    const float* __restrict__ tau0, float* __restrict__ out)
{
    const int b  = blockIdx.x;
    const int tx = threadIdx.x;
    const int H  = tx >> 8;
    const int U  = tx & 255;
    const int r  = b;

    __shared__ u64   GnP[120];
    __shared__ float4 Ds4[60];
    __shared__ float pf[2 * NM];
    __shared__ float taus[NN];
    __shared__ float msh[NN], vsh[NN];
    __shared__ float wsum[16], wsum2[16];
    __shared__ float lsh;
    float* GnF = (float*)GnP;
    const ulonglong2* At8 = (const ulonglong2*)g_At4;
    const ulonglong2* Ab8 = (const ulonglong2*)g_Ab4;
    const ulonglong2* Ds8 = (const ulonglong2*)Ds4;
    const ulonglong2* GnP2 = (const ulonglong2*)GnP;

    unsigned bartgt = (ld_acq(&g_barcnt) / PER_LAUNCH) * PER_LAUNCH + NB;
    unsigned gbase[4];
    gbase[0] = (ld_acq(&g_gc[0]) / 1920u) * 1920u;
    gbase[1] = (ld_acq(&g_gc[1]) / 1920u) * 1920u;
    gbase[2] = (ld_acq(&g_gc[2]) / 1680u) * 1680u;
    gbase[3] = (ld_acq(&g_gc[3]) / 1680u) * 1680u;

    // ---- init ----
    if (tx < 60) {
        int e = b * 60 + tx, kb = e / NM, j = e % NM;
        g_At4[e] = *(const float4*)(A + j * NN + 16 + 4 * kb);
        float4 v;
        v.x = A[(4 * kb + 0) * NN + 16 + j];
        v.y = A[(4 * kb + 1) * NN + 16 + j];
        v.z = A[(4 * kb + 2) * NN + 16 + j];
        v.w = A[(4 * kb + 3) * NN + 16 + j];
        g_Ab4[e] = v;
    }
    if (b == 0) {
        ((float*)g_S2buf)[tx] = 0.f;
        ((float*)g_S2buf)[tx + 512] = 0.f;
        if (tx < 4) g_Lbuf[tx] = 0.f;
    }
    float gl = 0.f, mg = 0.f, vg = 0.f;
    if (H == 0 && U < NM) gl = Gl0[r * NM + U];
    if (tx < NN) { taus[tx] = tau0[tx]; msh[tx] = 0.f; vsh[tx] = 0.f; }
    GRIDBAR();  // barrier #1

    double b1t = 1.0, b2t = 1.0;
    float bc1p = 1.f, bc2p = 1.f;
    int stop = 0;

    for (int t = 0; t < ITERS; ++t) {
        b1t *= 0.9; b2t *= 0.999;
        const float bc1c = (float)(1.0 / (1.0 - b1t));
        const float bc2c = (float)(1.0 / (1.0 - b2t));
        const int cs = t & 3;
        const int zs = (t + 1) & 3;

        // ================= HEAD =================
        if (t > 0) {
            const int ws = (t - 1) & 3;
            unsigned tgt = gbase[ws] + ((unsigned)((t - 1) >> 2) + 1u) * (unsigned)NB;
            if (tx == 0) { while (ld_acq(&g_gc[ws]) < tgt) __nanosleep(32); }
            __syncthreads();
            float s2v = 0.f;
            if (tx < 256) s2v = ldcg(&g_S2buf[ws][tx]);                 // READ ONLY
            if (t >= 2 && tx == 0) lsh = ldcg(&g_Lbuf[(t - 2) & 3]);    // READ ONLY
            if (!stop && tx < 256) {
                float g = -(2.f / 61440.f) * s2v;
                float mm = 0.9f * msh[tx] + 0.1f * g;
                float vv = 0.999f * vsh[tx] + 0.001f * g * g;
                msh[tx] = mm; vsh[tx] = vv;
                taus[tx] -= 0.1f * (mm * bc1p) / (sqrtf(vv * bc2p) + 1e-8f);
            }
        }
        if (H == 0 && U < NM) GnF[U] = -2.f * sigm(gl);
        // only block 0 zeroes next-write slots (ordered via counter waits)
        if (b == 0 && tx < 256) g_S2buf[zs][tx] = 0.f;
        if (b == 0 && tx == 0) g_Lbuf[zs] = 0.f;
        __syncthreads();   // syncA
        if (t >= 2 && !stop && lsh < 1e-3f) stop = 1;

        if (!stop) {
            float w = 0.f;
            if (H == 1 && U < NM)
                w = (-0.5f * GnF[U]) * fmaxf(taus[r] - taus[16 + U] + 0.1f, 0.f);
            WRED(w, wsum2);
            if (tx >= 16 && tx < 256) {
                const int m = tx;
                float e0 = fmaxf(taus[r] - taus[m] + 0.1f, 0.f);
                redadd(&g_S2buf[cs][m], (-0.5f * GnF[m - 16]) * e0);
            }
        }
        __threadfence();
        __syncthreads();   // syncB
        if (tx == 0) {
            if (!stop) {
                redadd(&g_S2buf[cs][r], -sum8(wsum2, 1));
                __threadfence();
            }
            atomicAdd(&g_gc[cs], 1u);
        }

        // ================= BODY =================
        if (!stop) {
            // forward with alternating traversal direction (L1 LRU-friendly);
            // product order change is output-safe: all |factors|<1 so the
            // full product underflows to exactly 0 in any order, and anyNZ
            // guards the exceptional case dynamically.
            if (U < NM) {
                u64 p0 = ONES2, p1 = ONES2;
                if ((t & 1) == 0) {
                    const ulonglong2* ap = At8 + (30 * H) * NM + U;
                    ulonglong2 an = ap[0];
                    #pragma unroll 6
                    for (int c = 0; c < 30; ++c) {
                        ulonglong2 a = an;
                        if (c < 29) an = ap[(c + 1) * NM];
                        ulonglong2 ga = GnP2[30 * H + c];
                        p0 = mul2_(p0, fma2_(a.x, ga.x, ONES2));
                        p1 = mul2_(p1, fma2_(a.y, ga.y, ONES2));
                    }
                } else {
                    const ulonglong2* ap = At8 + (30 * H + 29) * NM + U;
                    ulonglong2 an = ap[0];
                    #pragma unroll 6
                    for (int c = 0; c < 30; ++c) {
                        ulonglong2 a = an;
                        if (c < 29) an = ap[-((c + 1) * NM)];
                        ulonglong2 ga = GnP2[30 * H + 29 - c];
                        p0 = mul2_(p0, fma2_(a.x, ga.x, ONES2));
                        p1 = mul2_(p1, fma2_(a.y, ga.y, ONES2));
                    }
                }
                F2 x0; x0.u = p0; F2 x1; x1.u = p1;
                pf[H * NM + U] = (x0.f.x * x0.f.y) * (x1.f.x * x1.f.y);
            }
            __syncthreads();

            float v = 0.f;
            int nz = 0;
            if (U < NM) {
                if (H == 0) {
                    float P = pf[U] * pf[NM + U];
                    float e = P - ((U == r) ? -1.f : 1.f);
                    v = e * e;
                    float ds = e * P * (1.f / 480.f);
                    ((float*)Ds4)[U] = ds;
                    nz = (ds != 0.f);
                } else {
                    float d = fmaxf(taus[r] - taus[16 + U] + 0.1f, 0.f);
                    v = (-0.5f * GnF[U]) * d * d;
                }
            }
            WRED(v, wsum);
            int anyNZ = __syncthreads_or(nz);
            if (tx == 0)
                redadd(&g_Lbuf[cs], sum8(wsum, 0) * (1.f / 960.f)
                                  + sum8(wsum, 1) * (1.f / 61440.f));

            if (anyNZ) {   // backward only if any Ds nonzero
                if (U < NM) {
                    const int k = U;
                    F2 gp; gp.f.x = GnF[k]; gp.f.y = GnF[k];
                    const u64 gn2 = gp.u;
                    float acc = 0.f;
                    bool bad = false;
                    const ulonglong2* abp = Ab8 + (30 * H) * NM + k;
                    ulonglong2 an = abp[0];
                    #pragma unroll 6
                    for (int c = 0; c < 30; ++c) {
                        ulonglong2 a = an;
                        if (c < 29) an = abp[(c + 1) * NM];
                        ulonglong2 dA = Ds8[30 * H + c];
                        u64 t01 = fma2_(a.x, gn2, ONES2);
                        u64 t23 = fma2_(a.y, gn2, ONES2);
                        u64 n01 = mul2_(dA.x, a.x);
                        u64 n23 = mul2_(dA.y, a.y);
                        QUADACC(t01, t23, n01, n23, acc, bad);
                    }
                    if (bad) {
                        acc = 0.f;
                        const float gn = GnF[k];
                        for (int c = 0; c < 30; ++c) {
                            int jb = 30 * H + c;
                            float4 a4 = g_Ab4[jb * NM + k];
                            float4 dA = Ds4[jb];
                            const float* av = (const float*)&a4;
                            const float* dv = (const float*)&dA;
                            #pragma unroll
                            for (int e2 = 0; e2 < 4; ++e2) {
                                float tA = fmaf(av[e2], gn, 1.f);
                                acc += (tA != 0.f) ? __fdividef(dv[e2] * av[e2], tA) : 0.f;
                            }
                        }
                    }
                    pf[H * NM + k] = acc;
                }
                __syncthreads();
            }

            if (H == 0 && U < NM) {   // Adam(G), step t
                const int k = U;
                float S = anyNZ ? (pf[k] + pf[NM + k]) : 0.f;
                float s = -0.5f * GnF[k];
                float d = fmaxf(taus[r] - taus[16 + k] + 0.1f, 0.f);
                float grad = (-2.f * S + d * d * (1.f / 61440.f)) * (s * (1.f - s));
                mg = 0.9f * mg + 0.1f * grad;
                vg = 0.999f * vg + 0.001f * grad * grad;
                gl -= 0.1f * (mg * bc1c) / (sqrtf(vg * bc2c) + 1e-8f);
            }
        }
        bc1p = bc1c; bc2p = bc2c;
    }

    // ---- final tau update (Adam step 29) ----
    {
        unsigned tgt = gbase[1] + 1920u;
        if (tx == 0) { while (ld_acq(&g_gc[1]) < tgt) __nanosleep(32); }
        __syncthreads();
        float s = (tx < 256) ? ldcg(&g_S2buf[1][tx]) : 0.f;
        if (!stop && tx < 256) {
            float g = -(2.f / 61440.f) * s;
            float mm = 0.9f * msh[tx] + 0.1f * g;
            float vv = 0.999f * vsh[tx] + 0.001f * g * g;
            taus[tx] -= 0.1f * (mm * bc1p) / (sqrtf(vv * bc2p) + 1e-8f);
        }
        __syncthreads();
    }

    // ---- epilogue: final loss at p_final ----
    if (H == 0 && U < NM) GnF[U] = -2.f * sigm(gl);
    __syncthreads();
    if (U < NM) {
        const ulonglong2* ap = At8 + (30 * H) * NM + U;
        ulonglong2 an = ap[0];
        u64 p0 = ONES2, p1 = ONES2;
        #pragma unroll 6
        for (int c = 0; c < 30; ++c) {
            ulonglong2 a = an;
            if (c < 29) an = ap[(c + 1) * NM];
            ulonglong2 ga = GnP2[30 * H + c];
            p0 = mul2_(p0, fma2_(a.x, ga.x, ONES2));
            p1 = mul2_(p1, fma2_(a.y, ga.y, ONES2));
        }
        F2 x0; x0.u = p0; F2 x1; x1.u = p1;
        pf[H * NM + U] = (x0.f.x * x0.f.y) * (x1.f.x * x1.f.y);
    }
    __syncthreads();
    {
        float v = 0.f;
        if (U < NM) {
            if (H == 0) {
                float P = pf[U] * pf[NM + U];
                float e = P - ((U == r) ? -1.f : 1.f);
                v = e * e;
            } else {
                float d = fmaxf(taus[r] - taus[16 + U] + 0.1f, 0.f);
                v = (-0.5f * GnF[U]) * d * d;
            }
        }
        WRED(v, wsum);
        __syncthreads();
        if (tx == 0)
            g_Lp[b] = sum8(wsum, 0) * (1.f / 960.f) + sum8(wsum, 1) * (1.f / 61440.f);
    }
    GRIDBAR();  // barrier #2
    if (b == 0) {
        float lv = 0.f;
        if (tx < 60) {
            float4 q = ldcg4(((const float4*)g_Lp) + tx);
            lv = (q.x + q.y) + (q.z + q.w);
        }
        WRED(lv, wsum);
        __syncthreads();
        if (tx == 0) out[0] = wsum[0] + wsum[1];
    }
}

// ---------------- launch ----------------
extern "C" void kernel_launch(void* const* d_in, const int* in_sizes, int n_in,
                              void* d_out, int out_size) {
    const float* A    = (const float*)d_in[0];
    const float* Gl0  = (const float*)d_in[1];
    const float* tau0 = (const float*)d_in[2];
    gflow<<<NB, NT>>>(A, Gl0, tau0, (float*)d_out);
}